// round 11
// baseline (speedup 1.0000x reference)
#include <cuda_runtime.h>
#include <cstdint>

// Accumulator + completion counter. Invariant: both are 0 at kernel entry and
// are restored to 0 by the finishing block => deterministic across graph
// replays. Single-node graph: no memset node needed.
__device__ float    g_sum   = 0.0f;
__device__ unsigned g_count = 0u;

// ---------------------------------------------------------------------------
// One warp per batch (grid = B x 32). Each warp:
//   1. Issues its 128-label target load (32 lanes x int4) first.
//   2. While in flight, computes BOTH clamped BCE log terms for its 6
//      (batch,class) entries (torch BCELoss: log clamped at -100).
//   3. OR-reduces the 6-bit presence mask. Presence-OR is monotone, so early
//      exit is exact: p(miss after 128 uniform labels) ~ 4e-10; adversarial
//      data degrades to a full (still correct) scan.
//   4. Selects present/absent term, shfl-reduces, adds the pre-scaled partial
//      into g_sum. The LAST block to arrive drains g_sum with atomicExch
//      (read + reset in one op) and writes out[0]. No memset node.
// ---------------------------------------------------------------------------
__global__ void __launch_bounds__(32, 32)
se_loss_onenode_kernel(const int* __restrict__ target,
                       const float* __restrict__ se_pred,
                       float* __restrict__ out,
                       int n_vec4_per_batch, int n_batches, int n_terms) {
    const int lane = threadIdx.x;
    const int b    = blockIdx.x;

    // --- issue the target load first (longest latency) ---
    const int4* __restrict__ t4 = reinterpret_cast<const int4*>(target)
                                  + (long long)b * n_vec4_per_batch;
    int4 v0 = make_int4(0, 0, 0, 0);
    const bool ld0 = (lane < n_vec4_per_batch);
    if (ld0) v0 = t4[lane];

    // --- overlap: BCE log terms for this batch (lanes 0..5) ---
    const int term_idx = b * 6 + lane;
    const bool term_valid = (lane < 6) && (term_idx < n_terms);
    float v_present = 0.0f, v_absent = 0.0f;
    if (term_valid) {
        const float p = se_pred[term_idx];
        v_present = -fmaxf(logf(p),    -100.0f);   // t = 1
        v_absent  = -fmaxf(log1pf(-p), -100.0f);   // t = 0
    }

    // --- presence mask ---
    unsigned acc = 0u;
    if (ld0) {
        acc = (1u << (v0.x & 31)) | (1u << (v0.y & 31)) |
              (1u << (v0.z & 31)) | (1u << (v0.w & 31));
    }
    acc = __reduce_or_sync(0xffffffffu, acc) & 0x3Fu;

    if (acc != 0x3Fu) {                          // cold path: finish the scan
        for (int base = 32; base < n_vec4_per_batch; base += 32) {
            int idx = base + lane;
            unsigned a = 0u;
            if (idx < n_vec4_per_batch) {
                int4 v = t4[idx];
                a = (1u << (v.x & 31)) | (1u << (v.y & 31)) |
                    (1u << (v.z & 31)) | (1u << (v.w & 31));
            }
            acc |= __reduce_or_sync(0xffffffffu, a) & 0x3Fu;
            if (acc == 0x3Fu) break;
        }
    }

    // --- select + reduce this batch's 6 terms ---
    float v = 0.0f;
    if (term_valid)
        v = ((acc >> lane) & 1u) ? v_present : v_absent;
    #pragma unroll
    for (int o = 4; o > 0; o >>= 1) v += __shfl_down_sync(0xffffffffu, v, o);

    // --- accumulate; last block drains + resets + writes out ---
    if (lane == 0) {
        atomicAdd(&g_sum, v / (float)n_terms);
        __threadfence();                                  // release
        unsigned prev = atomicAdd(&g_count, 1u);
        if (prev == (unsigned)(n_batches - 1)) {          // last to arrive
            __threadfence();                              // acquire
            float total = atomicExch(&g_sum, 0.0f);       // read + reset
            out[0] = total;
            g_count = 0u;                                 // restore invariant
        }
    }
}

// ---------------------------------------------------------------------------
extern "C" void kernel_launch(void* const* d_in, const int* in_sizes, int n_in,
                              void* d_out, int out_size) {
    // Resolve inputs by size: se_pred has 64*6 = 384 elements; target is huge.
    int se_idx = 0, tg_idx = 1;
    if (n_in >= 2 && in_sizes[0] > in_sizes[1]) { se_idx = 1; tg_idx = 0; }

    const float* se_pred = (const float*)d_in[se_idx];
    const int*   target  = (const int*)d_in[tg_idx];
    float* out = (float*)d_out;

    const int n_terms   = in_sizes[se_idx];        // 384
    const int B         = n_terms / 6;             // 64
    const int per_batch = in_sizes[tg_idx] / B;    // 262144 int32 labels
    const int n_vec4    = per_batch / 4;           // int4 count per batch

    se_loss_onenode_kernel<<<B, 32>>>(target, se_pred, out, n_vec4, B, n_terms);
}